// round 14
// baseline (speedup 1.0000x reference)
#include <cuda_runtime.h>
#include <math.h>
#define G 128
#define NT 512
#define TT 4800
typedef unsigned long long u64;
typedef unsigned int u32;

// SMEM float offsets (R10 layout + V1/PREO/PRE2S tail)
#define OFF_G1I 0
#define OFF_G1H 6144
#define OFF_G2I 12288
#define OFF_G2H 18816
#define OFF_F1W 24960
#define OFF_F2W 27136
#define OFF_F3W 29312
#define OFF_W0  31360
#define OFF_G1B 31872
#define OFF_G2B 31888
#define OFF_F1B 31904
#define OFF_F2B 31908
#define OFF_F3B 31912
#define OFF_ACTA 31916
#define OFF_ACTH 34092
#define OFF_ACTH2 36140
#define OFF_AUX 38188
#define OFF_STAG 38572
#define OFF_SAMP 38764
#define OFF_V1   38768
#define OFF_PREO 38780
#define OFF_PRE2S 38796
#define SMEMF 38844
#define SMEM_BYTES (SMEMF*4)

__device__ float g_x2[2048], g_x3[2048], g_y1[2048], g_y2[2048];
__device__ float g_h1[2][2048], g_h2[2][2048];
__device__ u64 g_cand[G*4];
__device__ float g_pre[(size_t)TT*2048];
__device__ float g_pre2[(size_t)TT*512*12];   // [t][n][g][b]
__device__ u32 g_fl[G*32];   // one 128B line per CTA; monotonic across replays

__device__ __forceinline__ u32 ld_acq(const u32* p){
    u32 v; asm volatile("ld.acquire.gpu.global.b32 %0,[%1];":"=r"(v):"l"(p):"memory"); return v;
}
__device__ __forceinline__ void st_rel(u32* p, u32 v){
    asm volatile("st.release.gpu.global.b32 [%0],%1;"::"l"(p),"r"(v):"memory");
}
__device__ __forceinline__ u64 pk2(float x){ u64 r; asm("mov.b64 %0,{%1,%1};":"=l"(r):"f"(x)); return r; }
__device__ __forceinline__ void fma2(u64& d,u64 a,u64 b){ asm("fma.rn.f32x2 %0,%1,%2,%0;":"+l"(d):"l"(a),"l"(b)); }
__device__ __forceinline__ u64 add2(u64 a,u64 b){ u64 r; asm("add.rn.f32x2 %0,%1,%2;":"=l"(r):"l"(a),"l"(b)); return r; }
__device__ __forceinline__ void unpk(u64 v,float& lo,float& hi){ asm("mov.b64 {%0,%1},%2;":"=f"(lo),"=f"(hi):"l"(v)); }
__device__ __forceinline__ void lds2(u64& a,u64& b,u32 addr){
    asm volatile("ld.shared.v2.u64 {%0,%1},[%2];":"=l"(a),"=l"(b):"r"(addr));
}

// proven flag-array grid barrier: per-CTA epoch base, monotonic across replays
#define BAR() do{ ep++; __syncthreads(); \
    if(tid==0) st_rel(&g_fl[bx*32],ep); \
    if(tid<G){ const u32* f=&g_fl[tid*32]; while((int)(ld_acq(f)-ep)<0){} } \
    __syncthreads(); }while(0)

__device__ __forceinline__ void ldx(float* dst,const float* src){
    ((float4*)dst)[threadIdx.x]=__ldcg((const float4*)src+threadIdx.x);
}

// 16-warp 3-gate GEMV, 4-quarter K split (proven R13): warp w = neuron(w>>2), quarter(w&3).
// Writes partials to SD[w*12 + g*4 + b].
__device__ __forceinline__ void gemv3q(float* sm,u32 smb,int offW,int offA,int K,int Kq,float* SD){
    const int tid=threadIdx.x,w=tid>>5,lane=tid&31,n=w>>2,q=w&3;
    const u32 aB=smb+(u32)offA*4u;
    const float* W0=sm+offW+n*3*K;
    const float* W1=W0+K; const float* W2=W1+K;
    u64 ac[6]={0,0,0,0,0,0};
    const int kb=q*Kq, ke=kb+Kq;
    #pragma unroll 2
    for(int k=kb+lane;k<ke;k+=32){
        u64 a01,a23; lds2(a01,a23,aB+(u32)k*16u);
        u64 w0=pk2(W0[k]),w1=pk2(W1[k]),w2=pk2(W2[k]);
        fma2(ac[0],w0,a01); fma2(ac[1],w0,a23);
        fma2(ac[2],w1,a01); fma2(ac[3],w1,a23);
        fma2(ac[4],w2,a01); fma2(ac[5],w2,a23);
    }
    #pragma unroll
    for(int o=16;o;o>>=1)
        #pragma unroll
        for(int j=0;j<6;j++) ac[j]=add2(ac[j],__shfl_xor_sync(~0u,ac[j],o));
    if(!lane){
        float* S=SD+w*12;
        unpk(ac[0],S[0],S[1]); unpk(ac[1],S[2],S[3]);
        unpk(ac[2],S[4],S[5]); unpk(ac[3],S[6],S[7]);
        unpk(ac[4],S[8],S[9]); unpk(ac[5],S[10],S[11]);
    }
}

// GRU2 stage (R10 proven, 16 warps: neuron, side, K-half)
__device__ __forceinline__ void gru_stage(float* sm,u32 smb,int offHH,int offI,int offH,int offB,
                                          int Kin,int n0,float* xo,float* ho){
    const int tid=threadIdx.x,w=tid>>5,lane=tid&31;
    const int n=w>>2,q=w&3,side=q>>1,half=q&1;
    const int K=side?512:Kin, Kh=K>>1;
    const u32 aB=smb+(u32)(side?offHH:OFF_ACTA)*4u;
    const float* W0=side?(sm+offH+n*1536):(sm+offI+n*3*Kin);
    const float* W1=W0+K; const float* W2=W1+K;
    u64 ac[6]={0,0,0,0,0,0};
    const int kb=half*Kh, ke=kb+Kh;
    #pragma unroll 2
    for(int k=kb+lane;k<ke;k+=32){
        u64 a01,a23; lds2(a01,a23,aB+(u32)k*16u);
        u64 w0=pk2(W0[k]),w1=pk2(W1[k]),w2=pk2(W2[k]);
        fma2(ac[0],w0,a01); fma2(ac[1],w0,a23);
        fma2(ac[2],w1,a01); fma2(ac[3],w1,a23);
        fma2(ac[4],w2,a01); fma2(ac[5],w2,a23);
    }
    #pragma unroll
    for(int o=16;o;o>>=1)
        #pragma unroll
        for(int j=0;j<6;j++) ac[j]=add2(ac[j],__shfl_xor_sync(~0u,ac[j],o));
    if(!lane){
        float* S=sm+OFF_STAG+w*12;
        unpk(ac[0],S[0],S[1]); unpk(ac[1],S[2],S[3]);
        unpk(ac[2],S[4],S[5]); unpk(ac[3],S[6],S[7]);
        unpk(ac[4],S[8],S[9]); unpk(ac[5],S[10],S[11]);
    }
    __syncthreads();
    if(tid<16){
        int nn=tid>>2,b=tid&3;
        const float* S=sm+OFF_STAG+nn*48;
        const float* B=sm+offB+nn*4;
        float ir=S[b]+S[12+b],    iz=S[4+b]+S[16+b],  in_=S[8+b]+S[20+b];
        float hr=S[24+b]+S[36+b], hz=S[28+b]+S[40+b], hn =S[32+b]+S[44+b];
        float r=1.f/(1.f+expf(-(ir+hr+B[0])));
        float z=1.f/(1.f+expf(-(iz+hz+B[1])));
        float nv=tanhf(in_+B[2]+r*(hn+B[3]));
        float hv=(1.f-z)*nv+z*sm[offHH+(n0+nn)*4+b];
        ho[(n0+nn)*4+b]=hv;
        xo[(n0+nn)*4+b]=sm[OFF_ACTA+(n0+nn)*4+b]+hv;
    }
}

// FC stage, 16 warps (R10 proven): neuron w>>2, K-quarter w&3.
__device__ __forceinline__ void fc_stage(float* sm,u32 smb,int offW,int offB,int K,int n0,
                                         float* dd,bool relu){
    const int tid=threadIdx.x,w=tid>>5,lane=tid&31,n=w>>2,kq=w&3,Kq=K>>2;
    const u32 aB=smb+(u32)OFF_ACTA*4u;
    const float* W=sm+offW+n*K;
    u64 a01=0,a23=0;
    const int kb=kq*Kq, ke=kb+Kq;
    #pragma unroll 2
    for(int k=kb+lane;k<ke;k+=32){
        u64 x01,x23; lds2(x01,x23,aB+(u32)k*16u);
        u64 ww=pk2(W[k]);
        fma2(a01,ww,x01); fma2(a23,ww,x23);
    }
    #pragma unroll
    for(int o=16;o;o>>=1){ a01=add2(a01,__shfl_xor_sync(~0u,a01,o)); a23=add2(a23,__shfl_xor_sync(~0u,a23,o)); }
    if(!lane){ float* S=sm+OFF_STAG+w*4; unpk(a01,S[0],S[1]); unpk(a23,S[2],S[3]); }
    __syncthreads();
    if(tid<16){
        int nn=tid>>2,b=tid&3;
        const float* S=sm+OFF_STAG+nn*16;
        float v=S[b]+S[4+b]+S[8+b]+S[12+b]+sm[offB+nn];
        if(relu)v=fmaxf(v,0.f);
        dd[(n0+nn)*4+b]=v;
    }
}

extern "C" __global__ void __launch_bounds__(NT,1) wavernn_kernel(
    const float* __restrict__ mel,   const float* __restrict__ aux,
    const float* __restrict__ WI,    const float* __restrict__ bI,
    const float* __restrict__ g1wih, const float* __restrict__ g1whh,
    const float* __restrict__ g1bih, const float* __restrict__ g1bhh,
    const float* __restrict__ g2wih, const float* __restrict__ g2whh,
    const float* __restrict__ g2bih, const float* __restrict__ g2bhh,
    const float* __restrict__ f1w,   const float* __restrict__ f1b,
    const float* __restrict__ f2w,   const float* __restrict__ f2b,
    const float* __restrict__ f3w,   const float* __restrict__ f3b,
    float* __restrict__ out)
{
    extern __shared__ float sm[];
    const int tid=threadIdx.x, bx=blockIdx.x, n0=bx*4;
    const u32 smb=(u32)__cvta_generic_to_shared(sm);
    u32 ep=ld_acq(&g_fl[bx*32]);   // own flag: race-free monotonic base

    // one-time: pre[t] = b_I + W_I[:,1:]*[mel,aux0]
    {
        int t0=bx*TT/G, t1=(bx+1)*TT/G;
        for(int p=0;p<4;p++){
            for(int i=tid;i<128*112;i+=NT){int j=i/112,c=i-j*112;sm[j*112+c]=__ldg(&WI[(p*128+j)*113+1+c]);}
            __syncthreads();
            int jl=tid>>2, bh=tid&3, j=p*128+jl;
            float bias=__ldg(&bI[j]);
            const float* Wr=sm+jl*112;
            for(int t=t0;t<t1;t++){
                float a=bias;
                const float* m=mel+((size_t)bh*TT+t)*80;
                const float* x=aux+((size_t)bh*TT+t)*128;
                #pragma unroll 8
                for(int c=0;c<80;c++) a=fmaf(Wr[c],__ldg(m+c),a);
                #pragma unroll 8
                for(int c=0;c<32;c++) a=fmaf(Wr[80+c],__ldg(x+c),a);
                g_pre[((size_t)t*512+j)*4+bh]=a;
            }
            __syncthreads();
        }
    }
    // weights into SMEM (R10 layout)
    for(int i=tid;i<6144;i+=NT){int j=i/1536,r=i-j*1536,g=r>>9,k=r&511;
        sm[OFF_G1I+i]=__ldg(&g1wih[(g*512+n0+j)*512+k]);
        sm[OFF_G1H+i]=__ldg(&g1whh[(g*512+n0+j)*512+k]);
        sm[OFF_G2H+i]=__ldg(&g2whh[(g*512+n0+j)*512+k]);}
    for(int i=tid;i<6528;i+=NT){int j=i/1632,r=i-j*1632,g=r/544,k=r-g*544;
        sm[OFF_G2I+i]=__ldg(&g2wih[(g*512+n0+j)*544+k]);}
    for(int i=tid;i<2176;i+=NT){int j=i/544,k=i-j*544;
        sm[OFF_F1W+i]=__ldg(&f1w[(n0+j)*544+k]); sm[OFF_F2W+i]=__ldg(&f2w[(n0+j)*544+k]);}
    for(int i=tid;i<2048;i+=NT) sm[OFF_F3W+i]=__ldg(&f3w[(n0+(i>>9))*512+(i&511)]);
    for(int i=tid;i<512;i+=NT)  sm[OFF_W0+i]=__ldg(&WI[i*113]);
    if(tid<16){
        int nn=tid>>2,c=tid&3,n=n0+nn; float v1,v2;
        if(c==0){v1=g1bih[n]+g1bhh[n];v2=g2bih[n]+g2bhh[n];}
        else if(c==1){v1=g1bih[512+n]+g1bhh[512+n];v2=g2bih[512+n]+g2bhh[512+n];}
        else if(c==2){v1=g1bih[1024+n];v2=g2bih[1024+n];}
        else{v1=g1bhh[1024+n];v2=g2bhh[1024+n];}
        sm[OFF_G1B+tid]=v1; sm[OFF_G2B+tid]=v2;
        g_h1[0][(n0+nn)*4+c]=0.f; g_h2[0][(n0+nn)*4+c]=0.f;
    }
    if(tid<4){sm[OFF_F1B+tid]=f1b[n0+tid];sm[OFF_F2B+tid]=f2b[n0+tid];sm[OFF_F3B+tid]=f3b[n0+tid];sm[OFF_SAMP+tid]=0.f;}
    __syncthreads();
    // v1[nn][g] = G1I[nn][g][:] . w0  (12 dots, 12 warps)
    if(tid<384){
        int w=tid>>5, lane=tid&31, nn=w/3, g=w-nn*3;
        const float* W=sm+OFF_G1I+nn*1536+g*512;
        float a=0.f;
        for(int k=lane;k<512;k+=32) a=fmaf(W[k],sm[OFF_W0+k],a);
        #pragma unroll
        for(int o=16;o;o>>=1) a+=__shfl_xor_sync(~0u,a,o);
        if(!lane) sm[OFF_V1+nn*3+g]=a;
    }
    BAR();   // g_pre complete everywhere (and v1/weights synced)

    // one-time: pre2[t][own n][g][b] = G1I . pre[t], double-buffered over t (no exchange)
    ((float4*)(sm+OFF_ACTA))[tid]=__ldcg((const float4*)g_pre+tid);
    for(int t=0;t<TT;t++){
        __syncthreads();
        int bufc=(t&1)?OFF_ACTH:OFF_ACTA, bufn=(t&1)?OFF_ACTA:OFF_ACTH;
        if(t+1<TT) ((float4*)(sm+bufn))[tid]=__ldcg((const float4*)g_pre+((size_t)(t+1)*512+tid));
        gemv3q(sm,smb,OFF_G1I,bufc,512,128,sm+OFF_STAG);
        __syncthreads();
        if(tid<48){
            int nn=tid/12, r=tid-nn*12;
            float v=sm[OFF_STAG+(nn*4+0)*12+r]+sm[OFF_STAG+(nn*4+1)*12+r]
                   +sm[OFF_STAG+(nn*4+2)*12+r]+sm[OFF_STAG+(nn*4+3)*12+r];
            g_pre2[((size_t)t*512+n0+nn)*12+r]=v;
        }
    }

    float* outL=out+4*TT;
    for(int t=0;t<TT;t++){
        const int p=t&1;
        // step top: prefetch h1,h2, own pre/pre2 slices, aux (sample already in SAMP)
        ((float4*)(sm+OFF_ACTH))[tid] =__ldcg((const float4*)g_h1[p]+tid);
        ((float4*)(sm+OFF_ACTH2))[tid]=__ldcg((const float4*)g_h2[p]+tid);
        if(tid<96){int seg=tid>>5,c=tid&31,col=(seg+1)*32+c;
            ((float4*)(sm+OFF_AUX))[seg*32+c]=make_float4(
                aux[((size_t)0*TT+t)*128+col],aux[((size_t)1*TT+t)*128+col],
                aux[((size_t)2*TT+t)*128+col],aux[((size_t)3*TT+t)*128+col]);}
        if(tid>=128&&tid<176){int i=tid-128;
            sm[OFF_PRE2S+i]=__ldcg(&g_pre2[((size_t)t*512+n0+(i/12))*12+(i%12)]);}
        if(tid>=192&&tid<208){int i=tid-192;
            sm[OFF_PREO+i]=__ldcg(&g_pre[((size_t)t*512+n0+(i>>2))*4+(i&3)]);}
        __syncthreads();
        // P1: GRU1 hidden GEMV (4 quarters) + rank-1 input combine
        gemv3q(sm,smb,OFF_G1H,OFF_ACTH,512,128,sm+OFF_STAG);
        __syncthreads();
        if(tid<16){
            int nn=tid>>2,b=tid&3;
            const float* S=sm+OFF_STAG;
            float hr=S[(nn*4+0)*12+b]+S[(nn*4+1)*12+b]+S[(nn*4+2)*12+b]+S[(nn*4+3)*12+b];
            float hz=S[(nn*4+0)*12+4+b]+S[(nn*4+1)*12+4+b]+S[(nn*4+2)*12+4+b]+S[(nn*4+3)*12+4+b];
            float hn=S[(nn*4+0)*12+8+b]+S[(nn*4+1)*12+8+b]+S[(nn*4+2)*12+8+b]+S[(nn*4+3)*12+8+b];
            float sb=sm[OFF_SAMP+b];
            const float* P2S=sm+OFF_PRE2S+nn*12;
            float ir =P2S[b]  +sb*sm[OFF_V1+nn*3+0];
            float iz =P2S[4+b]+sb*sm[OFF_V1+nn*3+1];
            float in_=P2S[8+b]+sb*sm[OFF_V1+nn*3+2];
            const float* B=sm+OFF_G1B+nn*4;
            float r=1.f/(1.f+expf(-(ir+hr+B[0])));
            float z=1.f/(1.f+expf(-(iz+hz+B[1])));
            float nv=tanhf(in_+B[2]+r*(hn+B[3]));
            float hv=(1.f-z)*nv+z*sm[OFF_ACTH+(n0+nn)*4+b];
            g_h1[p^1][(n0+nn)*4+b]=hv;
            float xown=sm[OFF_PREO+nn*4+b]+sm[OFF_W0+n0+nn]*sb;
            g_x2[(n0+nn)*4+b]=xown+hv;
        }
        BAR();
        // P2: GRU2 (R10 verbatim)
        ldx(sm+OFF_ACTA,g_x2);
        if(tid<32) ((float4*)(sm+OFF_ACTA))[512+tid]=((const float4*)(sm+OFF_AUX))[tid];
        __syncthreads();
        gru_stage(sm,smb,OFF_ACTH2,OFF_G2I,OFF_G2H,OFF_G2B,544,n0,g_x3,g_h2[p^1]);
        BAR();
        // P3: fc1
        ldx(sm+OFF_ACTA,g_x3);
        if(tid<32) ((float4*)(sm+OFF_ACTA))[512+tid]=((const float4*)(sm+OFF_AUX))[32+tid];
        __syncthreads();
        fc_stage(sm,smb,OFF_F1W,OFF_F1B,544,n0,g_y1,true);
        BAR();
        // P4: fc2
        ldx(sm+OFF_ACTA,g_y1);
        if(tid<32) ((float4*)(sm+OFF_ACTA))[512+tid]=((const float4*)(sm+OFF_AUX))[64+tid];
        __syncthreads();
        fc_stage(sm,smb,OFF_F2W,OFF_F2B,544,n0,g_y2,true);
        BAR();
        // P5: fc3 + argmax keys (R10 verbatim)
        ldx(sm+OFF_ACTA,g_y2);
        __syncthreads();
        {
            const int wd=tid>>5,lane=tid&31,n=wd>>2,kq=wd&3;
            const u32 aB=smb+(u32)OFF_ACTA*4u;
            const float* W=sm+OFF_F3W+n*512;
            u64 a01=0,a23=0;
            #pragma unroll 2
            for(int k=kq*128+lane;k<kq*128+128;k+=32){
                u64 x01,x23; lds2(x01,x23,aB+(u32)k*16u);
                u64 ww=pk2(W[k]);
                fma2(a01,ww,x01); fma2(a23,ww,x23);
            }
            #pragma unroll
            for(int o=16;o;o>>=1){ a01=add2(a01,__shfl_xor_sync(~0u,a01,o)); a23=add2(a23,__shfl_xor_sync(~0u,a23,o)); }
            if(!lane){ float* S=sm+OFF_STAG+wd*4; unpk(a01,S[0],S[1]); unpk(a23,S[2],S[3]); }
            __syncthreads();
            if(tid<16){
                int nn=tid>>2,b=tid&3;
                const float* S=sm+OFF_STAG+nn*16;
                float v=S[b]+S[4+b]+S[8+b]+S[12+b]+sm[OFF_F3B+nn];
                outL[((size_t)b*TT+t)*512+n0+nn]=v;
                u32 u=__float_as_uint(v); u=(u&0x80000000u)?~u:(u|0x80000000u);
                u64 key=((u64)u<<32)|(u32)(511-(n0+nn));
                u64 v1=__shfl_xor_sync(0xffffu,key,4); if(v1>key)key=v1;
                u64 v2=__shfl_xor_sync(0xffffu,key,8); if(v2>key)key=v2;
                if(tid<4) g_cand[bx*4+tid]=key;
            }
        }
        BAR();
        // argmax all-reduce (R10 verbatim): warp w = batch w
        if(tid<128){
            int wd=tid>>5,lane=tid&31;
            u64 c=0ull;
            #pragma unroll
            for(int j=0;j<4;j++){ u64 v=__ldcg(&g_cand[(lane+32*j)*4+wd]); if(v>c)c=v; }
            #pragma unroll
            for(int o=16;o;o>>=1){ u64 v=__shfl_xor_sync(~0u,c,o); if(v>c)c=v; }
            if(lane==0){
                int idx=511-(int)(c&0xffffffffull);
                float s=2.f*(float)idx/511.f-1.f;
                sm[OFF_SAMP+wd]=s;
                if(bx==0) out[wd*TT+t]=s;
            }
        }
        __syncthreads();
    }
}

extern "C" void kernel_launch(void* const* d_in, const int* in_sizes, int n_in,
                              void* d_out, int out_size){
    (void)in_sizes;(void)n_in;(void)out_size;
    cudaFuncSetAttribute(wavernn_kernel, cudaFuncAttributeMaxDynamicSharedMemorySize, SMEM_BYTES);
    wavernn_kernel<<<G,NT,SMEM_BYTES>>>(
        (const float*)d_in[0],(const float*)d_in[1],(const float*)d_in[2],
        (const float*)d_in[3],(const float*)d_in[4],(const float*)d_in[5],
        (const float*)d_in[6],(const float*)d_in[7],(const float*)d_in[8],
        (const float*)d_in[9],(const float*)d_in[10],(const float*)d_in[11],
        (const float*)d_in[12],(const float*)d_in[13],(const float*)d_in[14],
        (const float*)d_in[15],(const float*)d_in[16],(const float*)d_in[17],
        (float*)d_out);
}

// round 15
// speedup vs baseline: 1.2221x; 1.2221x over previous
#include <cuda_runtime.h>
#include <math.h>
#define G 128
#define NT 512
#define TT 4800
typedef unsigned long long u64;
typedef unsigned int u32;

// SMEM float offsets (R10 layout)
#define OFF_G1I 0
#define OFF_G1H 6144
#define OFF_G2I 12288
#define OFF_G2H 18816
#define OFF_F1W 24960
#define OFF_F2W 27136
#define OFF_F3W 29312
#define OFF_W0  31360
#define OFF_G1B 31872
#define OFF_G2B 31888
#define OFF_F1B 31904
#define OFF_F2B 31908
#define OFF_F3B 31912
#define OFF_ACTA 31916
#define OFF_ACTH 34092
#define OFF_ACTH2 36140
#define OFF_AUX 38188
#define OFF_STAG 38572
#define OFF_SAMP 38764
#define SMEMF 38768
#define SMEM_BYTES (SMEMF*4)

__device__ float g_x2[2048], g_x3[2048], g_y1[2048], g_y2[2048];
__device__ float g_h1[2][2048], g_h2[2][2048];
__device__ u64 g_cand[G*4];
__device__ float g_pre[(size_t)TT*2048];
__device__ u32 g_fl[G*32];                     // init barrier (proven flag array)
__device__ __align__(128) u32 g_ctr[32];       // step barrier counter, own 128B line

__device__ __forceinline__ u32 ld_acq(const u32* p){
    u32 v; asm volatile("ld.acquire.gpu.global.b32 %0,[%1];":"=r"(v):"l"(p):"memory"); return v;
}
__device__ __forceinline__ void st_rel(u32* p, u32 v){
    asm volatile("st.release.gpu.global.b32 [%0],%1;"::"l"(p),"r"(v):"memory");
}
__device__ __forceinline__ u64 pk2(float x){ u64 r; asm("mov.b64 %0,{%1,%1};":"=l"(r):"f"(x)); return r; }
__device__ __forceinline__ void fma2(u64& d,u64 a,u64 b){ asm("fma.rn.f32x2 %0,%1,%2,%0;":"+l"(d):"l"(a),"l"(b)); }
__device__ __forceinline__ u64 add2(u64 a,u64 b){ u64 r; asm("add.rn.f32x2 %0,%1,%2;":"=l"(r):"l"(a),"l"(b)); return r; }
__device__ __forceinline__ void unpk(u64 v,float& lo,float& hi){ asm("mov.b64 {%0,%1},%2;":"=f"(lo),"=f"(hi):"l"(v)); }
__device__ __forceinline__ void lds2(u64& a,u64& b,u32 addr){
    asm volatile("ld.shared.v2.u64 {%0,%1},[%2];":"=l"(a),"=l"(b):"r"(addr));
}

// init barrier: proven flag array (race-free monotonic base from own flag)
#define BAR() do{ ep++; __syncthreads(); \
    if(tid==0) st_rel(&g_fl[bx*32],ep); \
    if(tid<G){ const u32* f=&g_fl[tid*32]; while((int)(ld_acq(f)-ep)<0){} } \
    __syncthreads(); }while(0)

// step barrier: single counter, 1 arriver + 1 poller per CTA (128x less poll traffic).
// base cb read at kernel entry — provably before any increment this launch
// (first CBAR is behind the init BAR, which all entry reads precede).
// release-RMW chain + acquire-load + __syncthreads gives full visibility.
#define CBAR() do{ bn++; __syncthreads(); \
    if(tid==0){ \
        asm volatile("red.release.gpu.global.add.u32 [%0],%1;"::"l"(&g_ctr[0]),"r"(1u):"memory"); \
        u32 tg=cb+bn*(u32)G; \
        while((int)(ld_acq(&g_ctr[0])-tg)<0){} \
    } \
    __syncthreads(); }while(0)

__device__ __forceinline__ void ldx(float* dst,const float* src){
    ((float4*)dst)[threadIdx.x]=__ldcg((const float4*)src+threadIdx.x);
}

// GRU stage, 16 warps (R10 proven): warp w → neuron w>>2, q=w&3: side=q>>1, K-half=q&1.
__device__ __forceinline__ void gru_stage(float* sm,u32 smb,int offHH,int offI,int offH,int offB,
                                          int Kin,int n0,float* xo,float* ho){
    const int tid=threadIdx.x,w=tid>>5,lane=tid&31;
    const int n=w>>2,q=w&3,side=q>>1,half=q&1;
    const int K=side?512:Kin, Kh=K>>1;
    const u32 aB=smb+(u32)(side?offHH:OFF_ACTA)*4u;
    const float* W0=side?(sm+offH+n*1536):(sm+offI+n*3*Kin);
    const float* W1=W0+K; const float* W2=W1+K;
    u64 ac[6]={0,0,0,0,0,0};
    const int kb=half*Kh, ke=kb+Kh;
    #pragma unroll 2
    for(int k=kb+lane;k<ke;k+=32){
        u64 a01,a23; lds2(a01,a23,aB+(u32)k*16u);
        u64 w0=pk2(W0[k]),w1=pk2(W1[k]),w2=pk2(W2[k]);
        fma2(ac[0],w0,a01); fma2(ac[1],w0,a23);
        fma2(ac[2],w1,a01); fma2(ac[3],w1,a23);
        fma2(ac[4],w2,a01); fma2(ac[5],w2,a23);
    }
    #pragma unroll
    for(int o=16;o;o>>=1)
        #pragma unroll
        for(int j=0;j<6;j++) ac[j]=add2(ac[j],__shfl_xor_sync(~0u,ac[j],o));
    if(!lane){
        float* S=sm+OFF_STAG+w*12;  // w = n*4 + side*2 + half
        unpk(ac[0],S[0],S[1]); unpk(ac[1],S[2],S[3]);
        unpk(ac[2],S[4],S[5]); unpk(ac[3],S[6],S[7]);
        unpk(ac[4],S[8],S[9]); unpk(ac[5],S[10],S[11]);
    }
    __syncthreads();
    if(tid<16){
        int nn=tid>>2,b=tid&3;
        const float* S=sm+OFF_STAG+nn*48;
        const float* B=sm+offB+nn*4;
        float ir=S[b]+S[12+b],    iz=S[4+b]+S[16+b],  in_=S[8+b]+S[20+b];
        float hr=S[24+b]+S[36+b], hz=S[28+b]+S[40+b], hn =S[32+b]+S[44+b];
        float r=1.f/(1.f+expf(-(ir+hr+B[0])));
        float z=1.f/(1.f+expf(-(iz+hz+B[1])));
        float nv=tanhf(in_+B[2]+r*(hn+B[3]));
        float hv=(1.f-z)*nv+z*sm[offHH+(n0+nn)*4+b];
        ho[(n0+nn)*4+b]=hv;
        xo[(n0+nn)*4+b]=sm[OFF_ACTA+(n0+nn)*4+b]+hv;
    }
}

// FC stage, 16 warps (R10 proven): neuron w>>2, K-quarter w&3.
__device__ __forceinline__ void fc_stage(float* sm,u32 smb,int offW,int offB,int K,int n0,
                                         float* dd,bool relu){
    const int tid=threadIdx.x,w=tid>>5,lane=tid&31,n=w>>2,kq=w&3,Kq=K>>2;
    const u32 aB=smb+(u32)OFF_ACTA*4u;
    const float* W=sm+offW+n*K;
    u64 a01=0,a23=0;
    const int kb=kq*Kq, ke=kb+Kq;
    #pragma unroll 2
    for(int k=kb+lane;k<ke;k+=32){
        u64 x01,x23; lds2(x01,x23,aB+(u32)k*16u);
        u64 ww=pk2(W[k]);
        fma2(a01,ww,x01); fma2(a23,ww,x23);
    }
    #pragma unroll
    for(int o=16;o;o>>=1){ a01=add2(a01,__shfl_xor_sync(~0u,a01,o)); a23=add2(a23,__shfl_xor_sync(~0u,a23,o)); }
    if(!lane){ float* S=sm+OFF_STAG+w*4; unpk(a01,S[0],S[1]); unpk(a23,S[2],S[3]); }
    __syncthreads();
    if(tid<16){
        int nn=tid>>2,b=tid&3;
        const float* S=sm+OFF_STAG+nn*16;
        float v=S[b]+S[4+b]+S[8+b]+S[12+b]+sm[offB+nn];
        if(relu)v=fmaxf(v,0.f);
        dd[(n0+nn)*4+b]=v;
    }
}

extern "C" __global__ void __launch_bounds__(NT,1) wavernn_kernel(
    const float* __restrict__ mel,   const float* __restrict__ aux,
    const float* __restrict__ WI,    const float* __restrict__ bI,
    const float* __restrict__ g1wih, const float* __restrict__ g1whh,
    const float* __restrict__ g1bih, const float* __restrict__ g1bhh,
    const float* __restrict__ g2wih, const float* __restrict__ g2whh,
    const float* __restrict__ g2bih, const float* __restrict__ g2bhh,
    const float* __restrict__ f1w,   const float* __restrict__ f1b,
    const float* __restrict__ f2w,   const float* __restrict__ f2b,
    const float* __restrict__ f3w,   const float* __restrict__ f3b,
    float* __restrict__ out)
{
    extern __shared__ float sm[];
    const int tid=threadIdx.x, bx=blockIdx.x, n0=bx*4;
    const u32 smb=(u32)__cvta_generic_to_shared(sm);
    u32 ep=ld_acq(&g_fl[bx*32]);       // init-barrier base (own flag, race-free)
    const u32 cb=ld_acq(&g_ctr[0]);    // counter base: read at entry, before ANY increment this launch
    u32 bn=0;

    // one-time: pre[t] = b_I + W_I[:,1:]*[mel,aux0] ; 512 threads = 128 rows x 4 batches
    {
        int t0=bx*TT/G, t1=(bx+1)*TT/G;
        for(int p=0;p<4;p++){
            for(int i=tid;i<128*112;i+=NT){int j=i/112,c=i-j*112;sm[j*112+c]=__ldg(&WI[(p*128+j)*113+1+c]);}
            __syncthreads();
            int jl=tid>>2, bh=tid&3, j=p*128+jl;
            float bias=__ldg(&bI[j]);
            const float* Wr=sm+jl*112;
            for(int t=t0;t<t1;t++){
                float a=bias;
                const float* m=mel+((size_t)bh*TT+t)*80;
                const float* x=aux+((size_t)bh*TT+t)*128;
                #pragma unroll 8
                for(int c=0;c<80;c++) a=fmaf(Wr[c],__ldg(m+c),a);
                #pragma unroll 8
                for(int c=0;c<32;c++) a=fmaf(Wr[80+c],__ldg(x+c),a);
                g_pre[((size_t)t*512+j)*4+bh]=a;
            }
            __syncthreads();
        }
    }
    // weights into SMEM (R10 layout)
    for(int i=tid;i<6144;i+=NT){int j=i/1536,r=i-j*1536,g=r>>9,k=r&511;
        sm[OFF_G1I+i]=__ldg(&g1wih[(g*512+n0+j)*512+k]);
        sm[OFF_G1H+i]=__ldg(&g1whh[(g*512+n0+j)*512+k]);
        sm[OFF_G2H+i]=__ldg(&g2whh[(g*512+n0+j)*512+k]);}
    for(int i=tid;i<6528;i+=NT){int j=i/1632,r=i-j*1632,g=r/544,k=r-g*544;
        sm[OFF_G2I+i]=__ldg(&g2wih[(g*512+n0+j)*544+k]);}
    for(int i=tid;i<2176;i+=NT){int j=i/544,k=i-j*544;
        sm[OFF_F1W+i]=__ldg(&f1w[(n0+j)*544+k]); sm[OFF_F2W+i]=__ldg(&f2w[(n0+j)*544+k]);}
    for(int i=tid;i<2048;i+=NT) sm[OFF_F3W+i]=__ldg(&f3w[(n0+(i>>9))*512+(i&511)]);
    for(int i=tid;i<512;i+=NT)  sm[OFF_W0+i]=__ldg(&WI[i*113]);
    if(tid<16){
        int nn=tid>>2,c=tid&3,n=n0+nn; float v1,v2;
        if(c==0){v1=g1bih[n]+g1bhh[n];v2=g2bih[n]+g2bhh[n];}
        else if(c==1){v1=g1bih[512+n]+g1bhh[512+n];v2=g2bih[512+n]+g2bhh[512+n];}
        else if(c==2){v1=g1bih[1024+n];v2=g2bih[1024+n];}
        else{v1=g1bhh[1024+n];v2=g2bhh[1024+n];}
        sm[OFF_G1B+tid]=v1; sm[OFF_G2B+tid]=v2;
        g_h1[0][(n0+nn)*4+c]=0.f; g_h2[0][(n0+nn)*4+c]=0.f;
    }
    if(tid<4){sm[OFF_F1B+tid]=f1b[n0+tid];sm[OFF_F2B+tid]=f2b[n0+tid];sm[OFF_F3B+tid]=f3b[n0+tid];sm[OFF_SAMP+tid]=0.f;}
    BAR();   // init flag-barrier: g_pre complete; also fences all base reads before any CBAR

    float* outL=out+4*TT;
    for(int t=0;t<TT;t++){
        const int p=t&1;
        // step top: sample known; prefetch pre/h1/h2/aux; build x locally (1 float4/thread)
        float4 sv=*(const float4*)(sm+OFF_SAMP);
        float4 p0=__ldcg((const float4*)g_pre+((size_t)t*512+tid));
        ((float4*)(sm+OFF_ACTH))[tid] =__ldcg((const float4*)g_h1[p]+tid);
        ((float4*)(sm+OFF_ACTH2))[tid]=__ldcg((const float4*)g_h2[p]+tid);
        if(tid<96){int seg=tid>>5,c=tid&31,col=(seg+1)*32+c;
            ((float4*)(sm+OFF_AUX))[seg*32+c]=make_float4(
                aux[((size_t)0*TT+t)*128+col],aux[((size_t)1*TT+t)*128+col],
                aux[((size_t)2*TT+t)*128+col],aux[((size_t)3*TT+t)*128+col]);}
        {
            float wv=sm[OFF_W0+tid]; float4 x;
            x.x=fmaf(wv,sv.x,p0.x);x.y=fmaf(wv,sv.y,p0.y);x.z=fmaf(wv,sv.z,p0.z);x.w=fmaf(wv,sv.w,p0.w);
            ((float4*)(sm+OFF_ACTA))[tid]=x;
        }
        __syncthreads();
        // P1: GRU1
        gru_stage(sm,smb,OFF_ACTH,OFF_G1I,OFF_G1H,OFF_G1B,512,n0,g_x2,g_h1[p^1]);
        CBAR();
        // P2: GRU2
        ldx(sm+OFF_ACTA,g_x2);
        if(tid<32) ((float4*)(sm+OFF_ACTA))[512+tid]=((const float4*)(sm+OFF_AUX))[tid];
        __syncthreads();
        gru_stage(sm,smb,OFF_ACTH2,OFF_G2I,OFF_G2H,OFF_G2B,544,n0,g_x3,g_h2[p^1]);
        CBAR();
        // P3: fc1
        ldx(sm+OFF_ACTA,g_x3);
        if(tid<32) ((float4*)(sm+OFF_ACTA))[512+tid]=((const float4*)(sm+OFF_AUX))[32+tid];
        __syncthreads();
        fc_stage(sm,smb,OFF_F1W,OFF_F1B,544,n0,g_y1,true);
        CBAR();
        // P4: fc2
        ldx(sm+OFF_ACTA,g_y1);
        if(tid<32) ((float4*)(sm+OFF_ACTA))[512+tid]=((const float4*)(sm+OFF_AUX))[64+tid];
        __syncthreads();
        fc_stage(sm,smb,OFF_F2W,OFF_F2B,544,n0,g_y2,true);
        CBAR();
        // P5: fc3 + argmax keys (16 warps: neuron w>>2, K-quarter w&3 of 512)
        ldx(sm+OFF_ACTA,g_y2);
        __syncthreads();
        {
            const int w=tid>>5,lane=tid&31,n=w>>2,kq=w&3;
            const u32 aB=smb+(u32)OFF_ACTA*4u;
            const float* W=sm+OFF_F3W+n*512;
            u64 a01=0,a23=0;
            #pragma unroll 2
            for(int k=kq*128+lane;k<kq*128+128;k+=32){
                u64 x01,x23; lds2(x01,x23,aB+(u32)k*16u);
                u64 ww=pk2(W[k]);
                fma2(a01,ww,x01); fma2(a23,ww,x23);
            }
            #pragma unroll
            for(int o=16;o;o>>=1){ a01=add2(a01,__shfl_xor_sync(~0u,a01,o)); a23=add2(a23,__shfl_xor_sync(~0u,a23,o)); }
            if(!lane){ float* S=sm+OFF_STAG+w*4; unpk(a01,S[0],S[1]); unpk(a23,S[2],S[3]); }
            __syncthreads();
            if(tid<16){
                int nn=tid>>2,b=tid&3;
                const float* S=sm+OFF_STAG+nn*16;
                float v=S[b]+S[4+b]+S[8+b]+S[12+b]+sm[OFF_F3B+nn];
                outL[((size_t)b*TT+t)*512+n0+nn]=v;
                u32 u=__float_as_uint(v); u=(u&0x80000000u)?~u:(u|0x80000000u);
                u64 key=((u64)u<<32)|(u32)(511-(n0+nn));
                u64 v1=__shfl_xor_sync(0xffffu,key,4); if(v1>key)key=v1;
                u64 v2=__shfl_xor_sync(0xffffu,key,8); if(v2>key)key=v2;
                if(tid<4) g_cand[bx*4+tid]=key;
            }
        }
        CBAR();
        // argmax all-reduce (R10 verbatim): warp w = batch w
        if(tid<128){
            int w=tid>>5,lane=tid&31;
            u64 c=0ull;
            #pragma unroll
            for(int j=0;j<4;j++){ u64 v=__ldcg(&g_cand[(lane+32*j)*4+w]); if(v>c)c=v; }
            #pragma unroll
            for(int o=16;o;o>>=1){ u64 v=__shfl_xor_sync(~0u,c,o); if(v>c)c=v; }
            if(lane==0){
                int idx=511-(int)(c&0xffffffffull);
                float s=2.f*(float)idx/511.f-1.f;
                sm[OFF_SAMP+w]=s;
                if(bx==0) out[w*TT+t]=s;
            }
        }
        __syncthreads();
    }
}

extern "C" void kernel_launch(void* const* d_in, const int* in_sizes, int n_in,
                              void* d_out, int out_size){
    (void)in_sizes;(void)n_in;(void)out_size;
    cudaFuncSetAttribute(wavernn_kernel, cudaFuncAttributeMaxDynamicSharedMemorySize, SMEM_BYTES);
    wavernn_kernel<<<G,NT,SMEM_BYTES>>>(
        (const float*)d_in[0],(const float*)d_in[1],(const float*)d_in[2],
        (const float*)d_in[3],(const float*)d_in[4],(const float*)d_in[5],
        (const float*)d_in[6],(const float*)d_in[7],(const float*)d_in[8],
        (const float*)d_in[9],(const float*)d_in[10],(const float*)d_in[11],
        (const float*)d_in[12],(const float*)d_in[13],(const float*)d_in[14],
        (const float*)d_in[15],(const float*)d_in[16],(const float*)d_in[17],
        (float*)d_out);
}

// round 16
// speedup vs baseline: 1.2435x; 1.0176x over previous
#include <cuda_runtime.h>
#include <math.h>
#define G 128
#define NT 512
#define TT 4800
typedef unsigned long long u64;
typedef unsigned int u32;

// SMEM float offsets (R15 layout + V1 + SH2)
#define OFF_G1I 0
#define OFF_G1H 6144
#define OFF_G2I 12288
#define OFF_G2H 18816
#define OFF_F1W 24960
#define OFF_F2W 27136
#define OFF_F3W 29312
#define OFF_W0  31360
#define OFF_G1B 31872
#define OFF_G2B 31888
#define OFF_F1B 31904
#define OFF_F2B 31908
#define OFF_F3B 31912
#define OFF_ACTA 31916
#define OFF_ACTH 34092
#define OFF_ACTH2 36140
#define OFF_AUX 38188
#define OFF_STAG 38572
#define OFF_SAMP 38764
#define OFF_V1   38768
#define OFF_SH2  38780
#define SMEMF 38972
#define SMEM_BYTES (SMEMF*4)

__device__ float g_x2[2048], g_x3[2048], g_y1[2048], g_y2[2048];
__device__ float g_h1[2][2048], g_h2[2][2048];
__device__ u64 g_cand[G*4];
__device__ float g_pre[(size_t)TT*2048];
__device__ u32 g_fl[G*32];                     // init barrier (proven flag array)
__device__ __align__(128) u32 g_ctr[32];       // step barrier counter, own 128B line

__device__ __forceinline__ u32 ld_acq(const u32* p){
    u32 v; asm volatile("ld.acquire.gpu.global.b32 %0,[%1];":"=r"(v):"l"(p):"memory"); return v;
}
__device__ __forceinline__ void st_rel(u32* p, u32 v){
    asm volatile("st.release.gpu.global.b32 [%0],%1;"::"l"(p),"r"(v):"memory");
}
__device__ __forceinline__ u64 pk2(float x){ u64 r; asm("mov.b64 %0,{%1,%1};":"=l"(r):"f"(x)); return r; }
__device__ __forceinline__ void fma2(u64& d,u64 a,u64 b){ asm("fma.rn.f32x2 %0,%1,%2,%0;":"+l"(d):"l"(a),"l"(b)); }
__device__ __forceinline__ u64 add2(u64 a,u64 b){ u64 r; asm("add.rn.f32x2 %0,%1,%2;":"=l"(r):"l"(a),"l"(b)); return r; }
__device__ __forceinline__ void unpk(u64 v,float& lo,float& hi){ asm("mov.b64 {%0,%1},%2;":"=f"(lo),"=f"(hi):"l"(v)); }
__device__ __forceinline__ void lds2(u64& a,u64& b,u32 addr){
    asm volatile("ld.shared.v2.u64 {%0,%1},[%2];":"=l"(a),"=l"(b):"r"(addr));
}

// init barrier: proven flag array
#define BAR() do{ ep++; __syncthreads(); \
    if(tid==0) st_rel(&g_fl[bx*32],ep); \
    if(tid<G){ const u32* f=&g_fl[tid*32]; while((int)(ld_acq(f)-ep)<0){} } \
    __syncthreads(); }while(0)

// counter barrier, split arrive/wait (proven R15; base cb read at kernel entry)
#define CARR() do{ bn++; __syncthreads(); \
    if(tid==0){ asm volatile("red.release.gpu.global.add.u32 [%0],%1;"::"l"(&g_ctr[0]),"r"(1u):"memory"); } \
    }while(0)
#define CWAITN(n) do{ if(tid==0){ u32 tg=cb+(u32)(n)*(u32)G; \
        while((int)(ld_acq(&g_ctr[0])-tg)<0){} } \
    __syncthreads(); }while(0)
#define CBAR() do{ CARR(); CWAITN(bn); }while(0)

__device__ __forceinline__ void ldx(float* dst,const float* src){
    ((float4*)dst)[threadIdx.x]=__ldcg((const float4*)src+threadIdx.x);
}

// P1 dual GEMV (R15 gru_stage GEMV body, K=512 both sides): side0 = G1I on ACTA(pre),
// side1 = G1H on ACTH(h1). Writes STAG[w*12+g*4+b], w=n*4+side*2+half.
__device__ __forceinline__ void gemv_dual(float* sm,u32 smb){
    const int tid=threadIdx.x,w=tid>>5,lane=tid&31;
    const int n=w>>2,q=w&3,side=q>>1,half=q&1;
    const u32 aB=smb+(u32)(side?OFF_ACTH:OFF_ACTA)*4u;
    const float* W0=sm+(side?OFF_G1H:OFF_G1I)+n*1536;
    const float* W1=W0+512; const float* W2=W1+512;
    u64 ac[6]={0,0,0,0,0,0};
    const int kb=half*256, ke=kb+256;
    #pragma unroll 2
    for(int k=kb+lane;k<ke;k+=32){
        u64 a01,a23; lds2(a01,a23,aB+(u32)k*16u);
        u64 w0=pk2(W0[k]),w1=pk2(W1[k]),w2=pk2(W2[k]);
        fma2(ac[0],w0,a01); fma2(ac[1],w0,a23);
        fma2(ac[2],w1,a01); fma2(ac[3],w1,a23);
        fma2(ac[4],w2,a01); fma2(ac[5],w2,a23);
    }
    #pragma unroll
    for(int o=16;o;o>>=1)
        #pragma unroll
        for(int j=0;j<6;j++) ac[j]=add2(ac[j],__shfl_xor_sync(~0u,ac[j],o));
    if(!lane){
        float* S=sm+OFF_STAG+w*12;
        unpk(ac[0],S[0],S[1]); unpk(ac[1],S[2],S[3]);
        unpk(ac[2],S[4],S[5]); unpk(ac[3],S[6],S[7]);
        unpk(ac[4],S[8],S[9]); unpk(ac[5],S[10],S[11]);
    }
}

// 16-warp 3-gate GEMV, 4-quarter K split (proven R13). Writes SD[w*12+g*4+b], w=n*4+q.
__device__ __forceinline__ void gemv3q(float* sm,u32 smb,int offW,int offA,int K,int Kq,float* SD){
    const int tid=threadIdx.x,w=tid>>5,lane=tid&31,n=w>>2,q=w&3;
    const u32 aB=smb+(u32)offA*4u;
    const float* W0=sm+offW+n*3*K;
    const float* W1=W0+K; const float* W2=W1+K;
    u64 ac[6]={0,0,0,0,0,0};
    const int kb=q*Kq, ke=kb+Kq;
    #pragma unroll 2
    for(int k=kb+lane;k<ke;k+=32){
        u64 a01,a23; lds2(a01,a23,aB+(u32)k*16u);
        u64 w0=pk2(W0[k]),w1=pk2(W1[k]),w2=pk2(W2[k]);
        fma2(ac[0],w0,a01); fma2(ac[1],w0,a23);
        fma2(ac[2],w1,a01); fma2(ac[3],w1,a23);
        fma2(ac[4],w2,a01); fma2(ac[5],w2,a23);
    }
    #pragma unroll
    for(int o=16;o;o>>=1)
        #pragma unroll
        for(int j=0;j<6;j++) ac[j]=add2(ac[j],__shfl_xor_sync(~0u,ac[j],o));
    if(!lane){
        float* S=SD+w*12;
        unpk(ac[0],S[0],S[1]); unpk(ac[1],S[2],S[3]);
        unpk(ac[2],S[4],S[5]); unpk(ac[3],S[6],S[7]);
        unpk(ac[4],S[8],S[9]); unpk(ac[5],S[10],S[11]);
    }
}

// FC stage, 16 warps (R15 proven)
__device__ __forceinline__ void fc_stage(float* sm,u32 smb,int offW,int offB,int K,int n0,
                                         float* dd,bool relu){
    const int tid=threadIdx.x,w=tid>>5,lane=tid&31,n=w>>2,kq=w&3,Kq=K>>2;
    const u32 aB=smb+(u32)OFF_ACTA*4u;
    const float* W=sm+offW+n*K;
    u64 a01=0,a23=0;
    const int kb=kq*Kq, ke=kb+Kq;
    #pragma unroll 2
    for(int k=kb+lane;k<ke;k+=32){
        u64 x01,x23; lds2(x01,x23,aB+(u32)k*16u);
        u64 ww=pk2(W[k]);
        fma2(a01,ww,x01); fma2(a23,ww,x23);
    }
    #pragma unroll
    for(int o=16;o;o>>=1){ a01=add2(a01,__shfl_xor_sync(~0u,a01,o)); a23=add2(a23,__shfl_xor_sync(~0u,a23,o)); }
    if(!lane){ float* S=sm+OFF_STAG+w*4; unpk(a01,S[0],S[1]); unpk(a23,S[2],S[3]); }
    __syncthreads();
    if(tid<16){
        int nn=tid>>2,b=tid&3;
        const float* S=sm+OFF_STAG+nn*16;
        float v=S[b]+S[4+b]+S[8+b]+S[12+b]+sm[offB+nn];
        if(relu)v=fmaxf(v,0.f);
        dd[(n0+nn)*4+b]=v;
    }
}

extern "C" __global__ void __launch_bounds__(NT,1) wavernn_kernel(
    const float* __restrict__ mel,   const float* __restrict__ aux,
    const float* __restrict__ WI,    const float* __restrict__ bI,
    const float* __restrict__ g1wih, const float* __restrict__ g1whh,
    const float* __restrict__ g1bih, const float* __restrict__ g1bhh,
    const float* __restrict__ g2wih, const float* __restrict__ g2whh,
    const float* __restrict__ g2bih, const float* __restrict__ g2bhh,
    const float* __restrict__ f1w,   const float* __restrict__ f1b,
    const float* __restrict__ f2w,   const float* __restrict__ f2b,
    const float* __restrict__ f3w,   const float* __restrict__ f3b,
    float* __restrict__ out)
{
    extern __shared__ float sm[];
    const int tid=threadIdx.x, bx=blockIdx.x, n0=bx*4;
    const u32 smb=(u32)__cvta_generic_to_shared(sm);
    u32 ep=ld_acq(&g_fl[bx*32]);       // init-barrier base
    const u32 cb=ld_acq(&g_ctr[0]);    // counter base: read at entry, before any increment
    u32 bn=0;

    // one-time: pre[t] = b_I + W_I[:,1:]*[mel,aux0]
    {
        int t0=bx*TT/G, t1=(bx+1)*TT/G;
        for(int p=0;p<4;p++){
            for(int i=tid;i<128*112;i+=NT){int j=i/112,c=i-j*112;sm[j*112+c]=__ldg(&WI[(p*128+j)*113+1+c]);}
            __syncthreads();
            int jl=tid>>2, bh=tid&3, j=p*128+jl;
            float bias=__ldg(&bI[j]);
            const float* Wr=sm+jl*112;
            for(int t=t0;t<t1;t++){
                float a=bias;
                const float* m=mel+((size_t)bh*TT+t)*80;
                const float* x=aux+((size_t)bh*TT+t)*128;
                #pragma unroll 8
                for(int c=0;c<80;c++) a=fmaf(Wr[c],__ldg(m+c),a);
                #pragma unroll 8
                for(int c=0;c<32;c++) a=fmaf(Wr[80+c],__ldg(x+c),a);
                g_pre[((size_t)t*512+j)*4+bh]=a;
            }
            __syncthreads();
        }
    }
    // weights into SMEM (R15 layout)
    for(int i=tid;i<6144;i+=NT){int j=i/1536,r=i-j*1536,g=r>>9,k=r&511;
        sm[OFF_G1I+i]=__ldg(&g1wih[(g*512+n0+j)*512+k]);
        sm[OFF_G1H+i]=__ldg(&g1whh[(g*512+n0+j)*512+k]);
        sm[OFF_G2H+i]=__ldg(&g2whh[(g*512+n0+j)*512+k]);}
    for(int i=tid;i<6528;i+=NT){int j=i/1632,r=i-j*1632,g=r/544,k=r-g*544;
        sm[OFF_G2I+i]=__ldg(&g2wih[(g*512+n0+j)*544+k]);}
    for(int i=tid;i<2176;i+=NT){int j=i/544,k=i-j*544;
        sm[OFF_F1W+i]=__ldg(&f1w[(n0+j)*544+k]); sm[OFF_F2W+i]=__ldg(&f2w[(n0+j)*544+k]);}
    for(int i=tid;i<2048;i+=NT) sm[OFF_F3W+i]=__ldg(&f3w[(n0+(i>>9))*512+(i&511)]);
    for(int i=tid;i<512;i+=NT)  sm[OFF_W0+i]=__ldg(&WI[i*113]);
    if(tid<16){
        int nn=tid>>2,c=tid&3,n=n0+nn; float v1,v2;
        if(c==0){v1=g1bih[n]+g1bhh[n];v2=g2bih[n]+g2bhh[n];}
        else if(c==1){v1=g1bih[512+n]+g1bhh[512+n];v2=g2bih[512+n]+g2bhh[512+n];}
        else if(c==2){v1=g1bih[1024+n];v2=g2bih[1024+n];}
        else{v1=g1bhh[1024+n];v2=g2bhh[1024+n];}
        sm[OFF_G1B+tid]=v1; sm[OFF_G2B+tid]=v2;
        g_h1[0][(n0+nn)*4+c]=0.f; g_h2[0][(n0+nn)*4+c]=0.f;
    }
    if(tid<4){sm[OFF_F1B+tid]=f1b[n0+tid];sm[OFF_F2B+tid]=f2b[n0+tid];sm[OFF_F3B+tid]=f3b[n0+tid];sm[OFF_SAMP+tid]=0.f;}
    __syncthreads();
    // v1[nn][g] = G1I[nn][g][:]·w0 (12 dots, proven R14)
    if(tid<384){
        int w=tid>>5, lane=tid&31, nn=w/3, g=w-nn*3;
        const float* W=sm+OFF_G1I+nn*1536+g*512;
        float a=0.f;
        for(int k=lane;k<512;k+=32) a=fmaf(W[k],sm[OFF_W0+k],a);
        #pragma unroll
        for(int o=16;o;o>>=1) a+=__shfl_xor_sync(~0u,a,o);
        if(!lane) sm[OFF_V1+nn*3+g]=a;
    }
    BAR();   // g_pre + v1 ready everywhere; fences base reads before any CARR

    float* outL=out+4*TT;
    for(int t=0;t<TT;t++){
        const int p=t&1;
        // step top: load pre, h1, h2, aux (all barrier-cleared ≥1 step ago)
        ((float4*)(sm+OFF_ACTA))[tid] =__ldcg((const float4*)g_pre+((size_t)t*512+tid));
        ((float4*)(sm+OFF_ACTH))[tid] =__ldcg((const float4*)g_h1[p]+tid);
        ((float4*)(sm+OFF_ACTH2))[tid]=__ldcg((const float4*)g_h2[p]+tid);
        if(tid<96){int seg=tid>>5,c=tid&31,col=(seg+1)*32+c;
            ((float4*)(sm+OFF_AUX))[seg*32+c]=make_float4(
                aux[((size_t)0*TT+t)*128+col],aux[((size_t)1*TT+t)*128+col],
                aux[((size_t)2*TT+t)*128+col],aux[((size_t)3*TT+t)*128+col]);}
        __syncthreads();
        // P1: dual GEMV on pre/h1 (sample-independent) — hides B5(t-1) detect
        gemv_dual(sm,smb);
        CWAITN(5*(u32)t);   // wait B5(t-1); trivially passes at t=0
        // argmax of step t-1 keys
        if(t&&tid<128){
            int wd=tid>>5,lane=tid&31;
            u64 c=0ull;
            #pragma unroll
            for(int j=0;j<4;j++){ u64 v=__ldcg(&g_cand[(lane+32*j)*4+wd]); if(v>c)c=v; }
            #pragma unroll
            for(int o=16;o;o>>=1){ u64 v=__shfl_xor_sync(~0u,c,o); if(v>c)c=v; }
            if(lane==0){
                int idx=511-(int)(c&0xffffffffull);
                float s=2.f*(float)idx/511.f-1.f;
                sm[OFF_SAMP+wd]=s;
                if(bx==0) out[wd*TT+(t-1)]=s;
            }
        }
        __syncthreads();
        // P1 epilogue: rank-1 sample correction (proven R14 math)
        if(tid<16){
            int nn=tid>>2,b=tid&3;
            const float* S=sm+OFF_STAG+nn*48;
            const float* B=sm+OFF_G1B+nn*4;
            float sb=sm[OFF_SAMP+b];
            float ir =S[b]   +S[12+b]+sb*sm[OFF_V1+nn*3+0];
            float iz =S[4+b] +S[16+b]+sb*sm[OFF_V1+nn*3+1];
            float in_=S[8+b] +S[20+b]+sb*sm[OFF_V1+nn*3+2];
            float hr=S[24+b]+S[36+b], hz=S[28+b]+S[40+b], hn=S[32+b]+S[44+b];
            float r=1.f/(1.f+expf(-(ir+hr+B[0])));
            float z=1.f/(1.f+expf(-(iz+hz+B[1])));
            float nv=tanhf(in_+B[2]+r*(hn+B[3]));
            float hv=(1.f-z)*nv+z*sm[OFF_ACTH+(n0+nn)*4+b];
            g_h1[p^1][(n0+nn)*4+b]=hv;
            float xo=sm[OFF_ACTA+(n0+nn)*4+b]+sm[OFF_W0+n0+nn]*sb;
            g_x2[(n0+nn)*4+b]=xo+hv;
        }
        CARR();                               // B1 arrive (bn=5t+1)
        // P2: hidden GEMV first (no x2 needed) — hides B1 detect
        gemv3q(sm,smb,OFF_G2H,OFF_ACTH2,512,128,sm+OFF_SH2);
        CWAITN(bn);                           // B1 wait
        ldx(sm+OFF_ACTA,g_x2);
        if(tid<32) ((float4*)(sm+OFF_ACTA))[512+tid]=((const float4*)(sm+OFF_AUX))[tid];
        __syncthreads();
        gemv3q(sm,smb,OFF_G2I,OFF_ACTA,544,136,sm+OFF_STAG);
        __syncthreads();
        if(tid<16){  // GRU2 combine (proven R13 4-quarter form)
            int nn=tid>>2,b=tid&3;
            const float* SI=sm+OFF_STAG+nn*48;
            const float* SH=sm+OFF_SH2+nn*48;
            const float* B=sm+OFF_G2B+nn*4;
            float ir=SI[b]+SI[12+b]+SI[24+b]+SI[36+b];
            float iz=SI[4+b]+SI[16+b]+SI[28+b]+SI[40+b];
            float in_=SI[8+b]+SI[20+b]+SI[32+b]+SI[44+b];
            float hr=SH[b]+SH[12+b]+SH[24+b]+SH[36+b];
            float hz=SH[4+b]+SH[16+b]+SH[28+b]+SH[40+b];
            float hn=SH[8+b]+SH[20+b]+SH[32+b]+SH[44+b];
            float r=1.f/(1.f+expf(-(ir+hr+B[0])));
            float z=1.f/(1.f+expf(-(iz+hz+B[1])));
            float nv=tanhf(in_+B[2]+r*(hn+B[3]));
            float hv=(1.f-z)*nv+z*sm[OFF_ACTH2+(n0+nn)*4+b];
            g_h2[p^1][(n0+nn)*4+b]=hv;
            g_x3[(n0+nn)*4+b]=sm[OFF_ACTA+(n0+nn)*4+b]+hv;
        }
        CBAR();                               // B2
        // P3: fc1 (R15 verbatim)
        ldx(sm+OFF_ACTA,g_x3);
        if(tid<32) ((float4*)(sm+OFF_ACTA))[512+tid]=((const float4*)(sm+OFF_AUX))[32+tid];
        __syncthreads();
        fc_stage(sm,smb,OFF_F1W,OFF_F1B,544,n0,g_y1,true);
        CBAR();                               // B3
        // P4: fc2
        ldx(sm+OFF_ACTA,g_y1);
        if(tid<32) ((float4*)(sm+OFF_ACTA))[512+tid]=((const float4*)(sm+OFF_AUX))[64+tid];
        __syncthreads();
        fc_stage(sm,smb,OFF_F2W,OFF_F2B,544,n0,g_y2,true);
        CBAR();                               // B4
        // P5: fc3 + argmax keys (R15 verbatim)
        ldx(sm+OFF_ACTA,g_y2);
        __syncthreads();
        {
            const int wd=tid>>5,lane=tid&31,n=wd>>2,kq=wd&3;
            const u32 aB=smb+(u32)OFF_ACTA*4u;
            const float* W=sm+OFF_F3W+n*512;
            u64 a01=0,a23=0;
            #pragma unroll 2
            for(int k=kq*128+lane;k<kq*128+128;k+=32){
                u64 x01,x23; lds2(x01,x23,aB+(u32)k*16u);
                u64 ww=pk2(W[k]);
                fma2(a01,ww,x01); fma2(a23,ww,x23);
            }
            #pragma unroll
            for(int o=16;o;o>>=1){ a01=add2(a01,__shfl_xor_sync(~0u,a01,o)); a23=add2(a23,__shfl_xor_sync(~0u,a23,o)); }
            if(!lane){ float* S=sm+OFF_STAG+wd*4; unpk(a01,S[0],S[1]); unpk(a23,S[2],S[3]); }
            __syncthreads();
            if(tid<16){
                int nn=tid>>2,b=tid&3;
                const float* S=sm+OFF_STAG+nn*16;
                float v=S[b]+S[4+b]+S[8+b]+S[12+b]+sm[OFF_F3B+nn];
                outL[((size_t)b*TT+t)*512+n0+nn]=v;
                u32 u=__float_as_uint(v); u=(u&0x80000000u)?~u:(u|0x80000000u);
                u64 key=((u64)u<<32)|(u32)(511-(n0+nn));
                u64 v1=__shfl_xor_sync(0xffffu,key,4); if(v1>key)key=v1;
                u64 v2=__shfl_xor_sync(0xffffu,key,8); if(v2>key)key=v2;
                if(tid<4) g_cand[bx*4+tid]=key;
            }
        }
        CARR();                               // B5 arrive (bn=5t+5), wait deferred to next P1
    }
    // tail: final sample from last step's keys
    if(bx==0){
        CWAITN(bn);
        if(tid<128){
            int wd=tid>>5,lane=tid&31;
            u64 c=0ull;
            #pragma unroll
            for(int j=0;j<4;j++){ u64 v=__ldcg(&g_cand[(lane+32*j)*4+wd]); if(v>c)c=v; }
            #pragma unroll
            for(int o=16;o;o>>=1){ u64 v=__shfl_xor_sync(~0u,c,o); if(v>c)c=v; }
            if(lane==0){
                int idx=511-(int)(c&0xffffffffull);
                out[wd*TT+TT-1]=2.f*(float)idx/511.f-1.f;
            }
        }
    }
}

extern "C" void kernel_launch(void* const* d_in, const int* in_sizes, int n_in,
                              void* d_out, int out_size){
    (void)in_sizes;(void)n_in;(void)out_size;
    cudaFuncSetAttribute(wavernn_kernel, cudaFuncAttributeMaxDynamicSharedMemorySize, SMEM_BYTES);
    wavernn_kernel<<<G,NT,SMEM_BYTES>>>(
        (const float*)d_in[0],(const float*)d_in[1],(const float*)d_in[2],
        (const float*)d_in[3],(const float*)d_in[4],(const float*)d_in[5],
        (const float*)d_in[6],(const float*)d_in[7],(const float*)d_in[8],
        (const float*)d_in[9],(const float*)d_in[10],(const float*)d_in[11],
        (const float*)d_in[12],(const float*)d_in[13],(const float*)d_in[14],
        (const float*)d_in[15],(const float*)d_in[16],(const float*)d_in[17],
        (float*)d_out);
}

// round 17
// speedup vs baseline: 1.2788x; 1.0284x over previous
#include <cuda_runtime.h>
#include <math.h>
#define G 128
#define NT 512
#define TT 4800
typedef unsigned long long u64;
typedef unsigned int u32;

// SMEM float offsets (R16 layout)
#define OFF_G1I 0
#define OFF_G1H 6144
#define OFF_G2I 12288
#define OFF_G2H 18816
#define OFF_F1W 24960
#define OFF_F2W 27136
#define OFF_F3W 29312
#define OFF_W0  31360
#define OFF_G1B 31872
#define OFF_G2B 31888
#define OFF_F1B 31904
#define OFF_F2B 31908
#define OFF_F3B 31912
#define OFF_ACTA 31916
#define OFF_ACTH 34092
#define OFF_ACTH2 36140
#define OFF_AUX 38188
#define OFF_STAG 38572
#define OFF_SAMP 38764
#define OFF_V1   38768
#define OFF_SH2  38780
#define SMEMF 38972
#define SMEM_BYTES (SMEMF*4)

__device__ float g_x2[2048], g_x3[2048], g_y1[2048], g_y2[2048];
__device__ float g_h1[2][2048], g_h2[2][2048];
__device__ u64 g_cand[G*4];
__device__ float g_pre[(size_t)TT*2048];
__device__ u32 g_fl[G*32];                     // init barrier (proven flag array)
__device__ __align__(128) u32 g_ctr[32];       // step barrier counter, own 128B line

__device__ __forceinline__ u32 ld_acq(const u32* p){
    u32 v; asm volatile("ld.acquire.gpu.global.b32 %0,[%1];":"=r"(v):"l"(p):"memory"); return v;
}
__device__ __forceinline__ void st_rel(u32* p, u32 v){
    asm volatile("st.release.gpu.global.b32 [%0],%1;"::"l"(p),"r"(v):"memory");
}
__device__ __forceinline__ u64 pk2(float x){ u64 r; asm("mov.b64 %0,{%1,%1};":"=l"(r):"f"(x)); return r; }
__device__ __forceinline__ void fma2(u64& d,u64 a,u64 b){ asm("fma.rn.f32x2 %0,%1,%2,%0;":"+l"(d):"l"(a),"l"(b)); }
__device__ __forceinline__ u64 add2(u64 a,u64 b){ u64 r; asm("add.rn.f32x2 %0,%1,%2;":"=l"(r):"l"(a),"l"(b)); return r; }
__device__ __forceinline__ void unpk(u64 v,float& lo,float& hi){ asm("mov.b64 {%0,%1},%2;":"=f"(lo),"=f"(hi):"l"(v)); }
__device__ __forceinline__ void lds2(u64& a,u64& b,u32 addr){
    asm volatile("ld.shared.v2.u64 {%0,%1},[%2];":"=l"(a),"=l"(b):"r"(addr));
}

// init barrier: proven flag array
#define BAR() do{ ep++; __syncthreads(); \
    if(tid==0) st_rel(&g_fl[bx*32],ep); \
    if(tid<G){ const u32* f=&g_fl[tid*32]; while((int)(ld_acq(f)-ep)<0){} } \
    __syncthreads(); }while(0)

// counter barrier, split arrive/wait (proven R15/R16)
#define CARR() do{ bn++; __syncthreads(); \
    if(tid==0){ asm volatile("red.release.gpu.global.add.u32 [%0],%1;"::"l"(&g_ctr[0]),"r"(1u):"memory"); } \
    }while(0)
#define CWAITN(n) do{ if(tid==0){ u32 tg=cb+(u32)(n)*(u32)G; \
        while((int)(ld_acq(&g_ctr[0])-tg)<0){} } \
    __syncthreads(); }while(0)
#define CBAR() do{ CARR(); CWAITN(bn); }while(0)

__device__ __forceinline__ void ldx(float* dst,const float* src){
    ((float4*)dst)[threadIdx.x]=__ldcg((const float4*)src+threadIdx.x);
}

// P1 dual GEMV (R16 proven) — FULL unroll (8 iters)
__device__ __forceinline__ void gemv_dual(float* sm,u32 smb){
    const int tid=threadIdx.x,w=tid>>5,lane=tid&31;
    const int n=w>>2,q=w&3,side=q>>1,half=q&1;
    const u32 aB=smb+(u32)(side?OFF_ACTH:OFF_ACTA)*4u;
    const float* W0=sm+(side?OFF_G1H:OFF_G1I)+n*1536;
    const float* W1=W0+512; const float* W2=W1+512;
    u64 ac[6]={0,0,0,0,0,0};
    const int kb=half*256+lane;
    #pragma unroll
    for(int i=0;i<8;i++){
        int k=kb+i*32;
        u64 a01,a23; lds2(a01,a23,aB+(u32)k*16u);
        u64 w0=pk2(W0[k]),w1=pk2(W1[k]),w2=pk2(W2[k]);
        fma2(ac[0],w0,a01); fma2(ac[1],w0,a23);
        fma2(ac[2],w1,a01); fma2(ac[3],w1,a23);
        fma2(ac[4],w2,a01); fma2(ac[5],w2,a23);
    }
    #pragma unroll
    for(int o=16;o;o>>=1)
        #pragma unroll
        for(int j=0;j<6;j++) ac[j]=add2(ac[j],__shfl_xor_sync(~0u,ac[j],o));
    if(!lane){
        float* S=sm+OFF_STAG+w*12;
        unpk(ac[0],S[0],S[1]); unpk(ac[1],S[2],S[3]);
        unpk(ac[2],S[4],S[5]); unpk(ac[3],S[6],S[7]);
        unpk(ac[4],S[8],S[9]); unpk(ac[5],S[10],S[11]);
    }
}

// 16-warp 3-gate GEMV, 4-quarter K split (R16 proven) — full unroll
__device__ __forceinline__ void gemv3q(float* sm,u32 smb,int offW,int offA,int K,int Kq,float* SD){
    const int tid=threadIdx.x,w=tid>>5,lane=tid&31,n=w>>2,q=w&3;
    const u32 aB=smb+(u32)offA*4u;
    const float* W0=sm+offW+n*3*K;
    const float* W1=W0+K; const float* W2=W1+K;
    u64 ac[6]={0,0,0,0,0,0};
    const int kb=q*Kq, ke=kb+Kq;
    #pragma unroll
    for(int k=kb+lane;k<ke;k+=32){
        u64 a01,a23; lds2(a01,a23,aB+(u32)k*16u);
        u64 w0=pk2(W0[k]),w1=pk2(W1[k]),w2=pk2(W2[k]);
        fma2(ac[0],w0,a01); fma2(ac[1],w0,a23);
        fma2(ac[2],w1,a01); fma2(ac[3],w1,a23);
        fma2(ac[4],w2,a01); fma2(ac[5],w2,a23);
    }
    #pragma unroll
    for(int o=16;o;o>>=1)
        #pragma unroll
        for(int j=0;j<6;j++) ac[j]=add2(ac[j],__shfl_xor_sync(~0u,ac[j],o));
    if(!lane){
        float* S=SD+w*12;
        unpk(ac[0],S[0],S[1]); unpk(ac[1],S[2],S[3]);
        unpk(ac[2],S[4],S[5]); unpk(ac[3],S[6],S[7]);
        unpk(ac[4],S[8],S[9]); unpk(ac[5],S[10],S[11]);
    }
}

// FC stage, 16 warps (R16 proven) — full unroll
__device__ __forceinline__ void fc_stage(float* sm,u32 smb,int offW,int offB,int K,int n0,
                                         float* dd,bool relu){
    const int tid=threadIdx.x,w=tid>>5,lane=tid&31,n=w>>2,kq=w&3,Kq=K>>2;
    const u32 aB=smb+(u32)OFF_ACTA*4u;
    const float* W=sm+offW+n*K;
    u64 a01=0,a23=0;
    const int kb=kq*Kq, ke=kb+Kq;
    #pragma unroll
    for(int k=kb+lane;k<ke;k+=32){
        u64 x01,x23; lds2(x01,x23,aB+(u32)k*16u);
        u64 ww=pk2(W[k]);
        fma2(a01,ww,x01); fma2(a23,ww,x23);
    }
    #pragma unroll
    for(int o=16;o;o>>=1){ a01=add2(a01,__shfl_xor_sync(~0u,a01,o)); a23=add2(a23,__shfl_xor_sync(~0u,a23,o)); }
    if(!lane){ float* S=sm+OFF_STAG+w*4; unpk(a01,S[0],S[1]); unpk(a23,S[2],S[3]); }
    __syncthreads();
    if(tid<16){
        int nn=tid>>2,b=tid&3;
        const float* S=sm+OFF_STAG+nn*16;
        float v=S[b]+S[4+b]+S[8+b]+S[12+b]+sm[offB+nn];
        if(relu)v=fmaxf(v,0.f);
        dd[(n0+nn)*4+b]=v;
    }
}

extern "C" __global__ void __launch_bounds__(NT,1) wavernn_kernel(
    const float* __restrict__ mel,   const float* __restrict__ aux,
    const float* __restrict__ WI,    const float* __restrict__ bI,
    const float* __restrict__ g1wih, const float* __restrict__ g1whh,
    const float* __restrict__ g1bih, const float* __restrict__ g1bhh,
    const float* __restrict__ g2wih, const float* __restrict__ g2whh,
    const float* __restrict__ g2bih, const float* __restrict__ g2bhh,
    const float* __restrict__ f1w,   const float* __restrict__ f1b,
    const float* __restrict__ f2w,   const float* __restrict__ f2b,
    const float* __restrict__ f3w,   const float* __restrict__ f3b,
    float* __restrict__ out)
{
    extern __shared__ float sm[];
    const int tid=threadIdx.x, bx=blockIdx.x, n0=bx*4;
    const u32 smb=(u32)__cvta_generic_to_shared(sm);
    u32 ep=ld_acq(&g_fl[bx*32]);       // init-barrier base
    const u32 cb=ld_acq(&g_ctr[0]);    // counter base: read at entry, before any increment
    u32 bn=0;

    // one-time: pre[t] = b_I + W_I[:,1:]*[mel,aux0]
    {
        int t0=bx*TT/G, t1=(bx+1)*TT/G;
        for(int p=0;p<4;p++){
            for(int i=tid;i<128*112;i+=NT){int j=i/112,c=i-j*112;sm[j*112+c]=__ldg(&WI[(p*128+j)*113+1+c]);}
            __syncthreads();
            int jl=tid>>2, bh=tid&3, j=p*128+jl;
            float bias=__ldg(&bI[j]);
            const float* Wr=sm+jl*112;
            for(int t=t0;t<t1;t++){
                float a=bias;
                const float* m=mel+((size_t)bh*TT+t)*80;
                const float* x=aux+((size_t)bh*TT+t)*128;
                #pragma unroll 8
                for(int c=0;c<80;c++) a=fmaf(Wr[c],__ldg(m+c),a);
                #pragma unroll 8
                for(int c=0;c<32;c++) a=fmaf(Wr[80+c],__ldg(x+c),a);
                g_pre[((size_t)t*512+j)*4+bh]=a;
            }
            __syncthreads();
        }
    }
    // weights into SMEM
    for(int i=tid;i<6144;i+=NT){int j=i/1536,r=i-j*1536,g=r>>9,k=r&511;
        sm[OFF_G1I+i]=__ldg(&g1wih[(g*512+n0+j)*512+k]);
        sm[OFF_G1H+i]=__ldg(&g1whh[(g*512+n0+j)*512+k]);
        sm[OFF_G2H+i]=__ldg(&g2whh[(g*512+n0+j)*512+k]);}
    for(int i=tid;i<6528;i+=NT){int j=i/1632,r=i-j*1632,g=r/544,k=r-g*544;
        sm[OFF_G2I+i]=__ldg(&g2wih[(g*512+n0+j)*544+k]);}
    for(int i=tid;i<2176;i+=NT){int j=i/544,k=i-j*544;
        sm[OFF_F1W+i]=__ldg(&f1w[(n0+j)*544+k]); sm[OFF_F2W+i]=__ldg(&f2w[(n0+j)*544+k]);}
    for(int i=tid;i<2048;i+=NT) sm[OFF_F3W+i]=__ldg(&f3w[(n0+(i>>9))*512+(i&511)]);
    for(int i=tid;i<512;i+=NT)  sm[OFF_W0+i]=__ldg(&WI[i*113]);
    if(tid<16){
        int nn=tid>>2,c=tid&3,n=n0+nn; float v1,v2;
        if(c==0){v1=g1bih[n]+g1bhh[n];v2=g2bih[n]+g2bhh[n];}
        else if(c==1){v1=g1bih[512+n]+g1bhh[512+n];v2=g2bih[512+n]+g2bhh[512+n];}
        else if(c==2){v1=g1bih[1024+n];v2=g2bih[1024+n];}
        else{v1=g1bhh[1024+n];v2=g2bhh[1024+n];}
        sm[OFF_G1B+tid]=v1; sm[OFF_G2B+tid]=v2;
        g_h1[0][(n0+nn)*4+c]=0.f; g_h2[0][(n0+nn)*4+c]=0.f;
    }
    if(tid<4){sm[OFF_F1B+tid]=f1b[n0+tid];sm[OFF_F2B+tid]=f2b[n0+tid];sm[OFF_F3B+tid]=f3b[n0+tid];sm[OFF_SAMP+tid]=0.f;}
    __syncthreads();
    // v1[nn][g] = G1I[nn][g][:]·w0 (12 dots, proven R14/R16)
    if(tid<384){
        int w=tid>>5, lane=tid&31, nn=w/3, g=w-nn*3;
        const float* W=sm+OFF_G1I+nn*1536+g*512;
        float a=0.f;
        for(int k=lane;k<512;k+=32) a=fmaf(W[k],sm[OFF_W0+k],a);
        #pragma unroll
        for(int o=16;o;o>>=1) a+=__shfl_xor_sync(~0u,a,o);
        if(!lane) sm[OFF_V1+nn*3+g]=a;
    }
    BAR();   // g_pre + v1 ready everywhere; fences base reads before any CARR

    float* outL=out+4*TT;
    for(int t=0;t<TT;t++){
        const int p=t&1;
        // step top: load pre, h1, h2, aux (all barrier-cleared ≥1 step ago)
        ((float4*)(sm+OFF_ACTA))[tid] =__ldcg((const float4*)g_pre+((size_t)t*512+tid));
        ((float4*)(sm+OFF_ACTH))[tid] =__ldcg((const float4*)g_h1[p]+tid);
        ((float4*)(sm+OFF_ACTH2))[tid]=__ldcg((const float4*)g_h2[p]+tid);
        if(tid<96){int seg=tid>>5,c=tid&31,col=(seg+1)*32+c;
            ((float4*)(sm+OFF_AUX))[seg*32+c]=make_float4(
                aux[((size_t)0*TT+t)*128+col],aux[((size_t)1*TT+t)*128+col],
                aux[((size_t)2*TT+t)*128+col],aux[((size_t)3*TT+t)*128+col]);}
        __syncthreads();
        // P1: dual GEMV on pre/h1 (sample-independent) — hides B5(t-1) detect
        gemv_dual(sm,smb);
        CWAITN(5*(u32)t);   // wait B5(t-1); trivially passes at t=0
        // argmax of step t-1 keys
        if(t&&tid<128){
            int wd=tid>>5,lane=tid&31;
            u64 c=0ull;
            #pragma unroll
            for(int j=0;j<4;j++){ u64 v=__ldcg(&g_cand[(lane+32*j)*4+wd]); if(v>c)c=v; }
            #pragma unroll
            for(int o=16;o;o>>=1){ u64 v=__shfl_xor_sync(~0u,c,o); if(v>c)c=v; }
            if(lane==0){
                int idx=511-(int)(c&0xffffffffull);
                float s=2.f*(float)idx/511.f-1.f;
                sm[OFF_SAMP+wd]=s;
                if(bx==0) out[wd*TT+(t-1)]=s;
            }
        }
        __syncthreads();
        // P1 epilogue: rank-1 sample correction (proven R14/R16 math)
        if(tid<16){
            int nn=tid>>2,b=tid&3;
            const float* S=sm+OFF_STAG+nn*48;
            const float* B=sm+OFF_G1B+nn*4;
            float sb=sm[OFF_SAMP+b];
            float ir =S[b]   +S[12+b]+sb*sm[OFF_V1+nn*3+0];
            float iz =S[4+b] +S[16+b]+sb*sm[OFF_V1+nn*3+1];
            float in_=S[8+b] +S[20+b]+sb*sm[OFF_V1+nn*3+2];
            float hr=S[24+b]+S[36+b], hz=S[28+b]+S[40+b], hn=S[32+b]+S[44+b];
            float r=1.f/(1.f+expf(-(ir+hr+B[0])));
            float z=1.f/(1.f+expf(-(iz+hz+B[1])));
            float nv=tanhf(in_+B[2]+r*(hn+B[3]));
            float hv=(1.f-z)*nv+z*sm[OFF_ACTH+(n0+nn)*4+b];
            g_h1[p^1][(n0+nn)*4+b]=hv;
            float xo=sm[OFF_ACTA+(n0+nn)*4+b]+sm[OFF_W0+n0+nn]*sb;
            g_x2[(n0+nn)*4+b]=xo+hv;
        }
        CARR();                               // B1 arrive (bn=5t+1)
        // P2: hidden GEMV first (no x2 needed) — hides B1 detect
        gemv3q(sm,smb,OFF_G2H,OFF_ACTH2,512,128,sm+OFF_SH2);
        CWAITN(bn);                           // B1 wait
        ldx(sm+OFF_ACTA,g_x2);
        if(tid<32) ((float4*)(sm+OFF_ACTA))[512+tid]=((const float4*)(sm+OFF_AUX))[tid];
        __syncthreads();
        gemv3q(sm,smb,OFF_G2I,OFF_ACTA,544,136,sm+OFF_STAG);
        __syncthreads();
        if(tid<16){  // GRU2 combine (proven R13/R16 4-quarter form)
            int nn=tid>>2,b=tid&3;
            const float* SI=sm+OFF_STAG+nn*48;
            const float* SH=sm+OFF_SH2+nn*48;
            const float* B=sm+OFF_G2B+nn*4;
            float ir=SI[b]+SI[12+b]+SI[24+b]+SI[36+b];
            float iz=SI[4+b]+SI[16+b]+SI[28+b]+SI[40+b];
            float in_=SI[8+b]+SI[20+b]+SI[32+b]+SI[44+b];
            float hr=SH[b]+SH[12+b]+SH[24+b]+SH[36+b];
            float hz=SH[4+b]+SH[16+b]+SH[28+b]+SH[40+b];
            float hn=SH[8+b]+SH[20+b]+SH[32+b]+SH[44+b];
            float r=1.f/(1.f+expf(-(ir+hr+B[0])));
            float z=1.f/(1.f+expf(-(iz+hz+B[1])));
            float nv=tanhf(in_+B[2]+r*(hn+B[3]));
            float hv=(1.f-z)*nv+z*sm[OFF_ACTH2+(n0+nn)*4+b];
            g_h2[p^1][(n0+nn)*4+b]=hv;
            g_x3[(n0+nn)*4+b]=sm[OFF_ACTA+(n0+nn)*4+b]+hv;
        }
        // aux2 copy hoisted off post-wait path (WAR-safe: gemv3q reads done at sync above)
        if(tid>=480) ((float4*)(sm+OFF_ACTA))[512+(tid-480)]=((const float4*)(sm+OFF_AUX))[32+(tid-480)];
        CBAR();                               // B2
        // P3: fc1
        ldx(sm+OFF_ACTA,g_x3);
        __syncthreads();
        fc_stage(sm,smb,OFF_F1W,OFF_F1B,544,n0,g_y1,true);
        // aux3 copy hoisted (fc_stage reads done at its internal sync; tid>=480 not in tid<16 epilogue)
        if(tid>=480) ((float4*)(sm+OFF_ACTA))[512+(tid-480)]=((const float4*)(sm+OFF_AUX))[64+(tid-480)];
        CBAR();                               // B3
        // P4: fc2
        ldx(sm+OFF_ACTA,g_y1);
        __syncthreads();
        fc_stage(sm,smb,OFF_F2W,OFF_F2B,544,n0,g_y2,true);
        CBAR();                               // B4
        // P5: fc3 + argmax keys
        ldx(sm+OFF_ACTA,g_y2);
        __syncthreads();
        {
            const int wd=tid>>5,lane=tid&31,n=wd>>2,kq=wd&3;
            const u32 aB=smb+(u32)OFF_ACTA*4u;
            const float* W=sm+OFF_F3W+n*512;
            u64 a01=0,a23=0;
            const int kb=kq*128+lane;
            #pragma unroll
            for(int i=0;i<4;i++){
                int k=kb+i*32;
                u64 x01,x23; lds2(x01,x23,aB+(u32)k*16u);
                u64 ww=pk2(W[k]);
                fma2(a01,ww,x01); fma2(a23,ww,x23);
            }
            #pragma unroll
            for(int o=16;o;o>>=1){ a01=add2(a01,__shfl_xor_sync(~0u,a01,o)); a23=add2(a23,__shfl_xor_sync(~0u,a23,o)); }
            if(!lane){ float* S=sm+OFF_STAG+wd*4; unpk(a01,S[0],S[1]); unpk(a23,S[2],S[3]); }
            __syncthreads();
            if(tid<16){
                int nn=tid>>2,b=tid&3;
                const float* S=sm+OFF_STAG+nn*16;
                float v=S[b]+S[4+b]+S[8+b]+S[12+b]+sm[OFF_F3B+nn];
                outL[((size_t)b*TT+t)*512+n0+nn]=v;
                u32 u=__float_as_uint(v); u=(u&0x80000000u)?~u:(u|0x80000000u);
                u64 key=((u64)u<<32)|(u32)(511-(n0+nn));
                u64 v1=__shfl_xor_sync(0xffffu,key,4); if(v1>key)key=v1;
                u64 v2=__shfl_xor_sync(0xffffu,key,8); if(v2>key)key=v2;
                if(tid<4) g_cand[bx*4+tid]=key;
            }
        }
        CARR();                               // B5 arrive (bn=5t+5), wait deferred to next P1
    }
    // tail: final sample from last step's keys
    if(bx==0){
        CWAITN(bn);
        if(tid<128){
            int wd=tid>>5,lane=tid&31;
            u64 c=0ull;
            #pragma unroll
            for(int j=0;j<4;j++){ u64 v=__ldcg(&g_cand[(lane+32*j)*4+wd]); if(v>c)c=v; }
            #pragma unroll
            for(int o=16;o;o>>=1){ u64 v=__shfl_xor_sync(~0u,c,o); if(v>c)c=v; }
            if(lane==0){
                int idx=511-(int)(c&0xffffffffull);
                out[wd*TT+TT-1]=2.f*(float)idx/511.f-1.f;
            }
        }
    }
}

extern "C" void kernel_launch(void* const* d_in, const int* in_sizes, int n_in,
                              void* d_out, int out_size){
    (void)in_sizes;(void)n_in;(void)out_size;
    cudaFuncSetAttribute(wavernn_kernel, cudaFuncAttributeMaxDynamicSharedMemorySize, SMEM_BYTES);
    wavernn_kernel<<<G,NT,SMEM_BYTES>>>(
        (const float*)d_in[0],(const float*)d_in[1],(const float*)d_in[2],
        (const float*)d_in[3],(const float*)d_in[4],(const float*)d_in[5],
        (const float*)d_in[6],(const float*)d_in[7],(const float*)d_in[8],
        (const float*)d_in[9],(const float*)d_in[10],(const float*)d_in[11],
        (const float*)d_in[12],(const float*)d_in[13],(const float*)d_in[14],
        (const float*)d_in[15],(const float*)d_in[16],(const float*)d_in[17],
        (float*)d_out);
}